// round 3
// baseline (speedup 1.0000x reference)
#include <cuda_runtime.h>
#include <math.h>

#define B_SZ 2
#define S_LEN 2048
#define NH 16
#define DH 64
#define DM 1024
#define M_ROWS (B_SZ * S_LEN)          // 4096
#define OUT_ELEMS (B_SZ * S_LEN * DM)  // 4,194,304

typedef unsigned long long ull;

// Packed fp32x2 FMA (FFMA2) — ptxas never auto-fuses this; PTX-only.
#define FMA2(d, a, b, c) \
    asm("fma.rn.f32x2 %0, %1, %2, %3;" : "=l"(d) : "l"(a), "l"(b), "l"(c))
#define PACK2(d, x) \
    asm("mov.b64 %0, {%1, %1};" : "=l"(d) : "r"(__float_as_uint(x)))
#define UNPACK2(lo, hi, in) \
    asm("mov.b64 {%0, %1}, %2;" : "=f"(lo), "=f"(hi) : "l"(in))

// Scratch (allocation-free rule: device globals)
__device__ float g_q[B_SZ * NH * S_LEN * DH];
__device__ float g_k[B_SZ * NH * S_LEN * DH];
__device__ float g_v[B_SZ * NH * S_LEN * DH];
__device__ float g_o[B_SZ * S_LEN * DM];

// ---------------------------------------------------------------------------
// Merged QKV projection: z selects (Q,Wq,bq)->g_q etc. 128x128 tile,
// 256 threads, 8x8 micro via 8x4 packed FFMA2, k-tile 16.
// Output in head-split layout [B,H,S,DH].
// ---------------------------------------------------------------------------
__global__ __launch_bounds__(256, 2)
void proj_qkv(const float* __restrict__ Q, const float* __restrict__ Kin,
              const float* __restrict__ V,
              const float* __restrict__ Wq, const float* __restrict__ Wk,
              const float* __restrict__ Wv,
              const float* __restrict__ bq, const float* __restrict__ bk,
              const float* __restrict__ bv,
              float* __restrict__ gq, float* __restrict__ gk,
              float* __restrict__ gv)
{
    __shared__ float As[16][132];   // [k][m] (transposed)
    __shared__ float Bs[16][132];   // [k][n] (natural)

    const float *A, *W, *bias;
    float* C;
    if (blockIdx.z == 0)      { A = Q;   W = Wq; bias = bq; C = gq; }
    else if (blockIdx.z == 1) { A = Kin; W = Wk; bias = bk; C = gk; }
    else                      { A = V;   W = Wv; bias = bv; C = gv; }

    const int tid = threadIdx.x;
    const int bm = blockIdx.x * 128;
    const int bn = blockIdx.y * 128;
    const int tx = tid & 15;
    const int ty = tid >> 4;

    ull acc[8][4] = {};

    for (int k0 = 0; k0 < DM; k0 += 16) {
        #pragma unroll
        for (int i = 0; i < 2; i++) {
            int lin = tid + i * 256;          // 0..511
            int r = lin >> 2;                 // 0..127
            int c4 = lin & 3;                 // 0..3
            float4 v = *(const float4*)&A[(size_t)(bm + r) * DM + k0 + c4 * 4];
            As[c4 * 4 + 0][r] = v.x; As[c4 * 4 + 1][r] = v.y;
            As[c4 * 4 + 2][r] = v.z; As[c4 * 4 + 3][r] = v.w;
        }
        #pragma unroll
        for (int i = 0; i < 2; i++) {
            int lin = tid + i * 256;
            int r = lin >> 5;                 // 0..15
            int c4 = lin & 31;
            *(float4*)&Bs[r][c4 * 4] =
                *(const float4*)&W[(size_t)(k0 + r) * DM + bn + c4 * 4];
        }
        __syncthreads();

        #pragma unroll
        for (int kk = 0; kk < 16; kk++) {
            float a8[8];
            *(float4*)&a8[0] = *(const float4*)&As[kk][ty * 8];
            *(float4*)&a8[4] = *(const float4*)&As[kk][ty * 8 + 4];
            ull b0 = *(const ull*)&Bs[kk][tx * 8 + 0];
            ull b1 = *(const ull*)&Bs[kk][tx * 8 + 2];
            ull b2 = *(const ull*)&Bs[kk][tx * 8 + 4];
            ull b3 = *(const ull*)&Bs[kk][tx * 8 + 6];
            #pragma unroll
            for (int i = 0; i < 8; i++) {
                ull ap; PACK2(ap, a8[i]);
                FMA2(acc[i][0], ap, b0, acc[i][0]);
                FMA2(acc[i][1], ap, b1, acc[i][1]);
                FMA2(acc[i][2], ap, b2, acc[i][2]);
                FMA2(acc[i][3], ap, b3, acc[i][3]);
            }
        }
        __syncthreads();
    }

    float bb[8];
    *(float4*)&bb[0] = *(const float4*)&bias[bn + tx * 8];
    *(float4*)&bb[4] = *(const float4*)&bias[bn + tx * 8 + 4];

    #pragma unroll
    for (int i = 0; i < 8; i++) {
        int row = bm + ty * 8 + i;
        int col0 = bn + tx * 8;
        float o[8];
        #pragma unroll
        for (int p = 0; p < 4; p++) UNPACK2(o[2*p], o[2*p+1], acc[i][p]);
        float4 v0, v1;
        v0.x = o[0] + bb[0]; v0.y = o[1] + bb[1];
        v0.z = o[2] + bb[2]; v0.w = o[3] + bb[3];
        v1.x = o[4] + bb[4]; v1.y = o[5] + bb[5];
        v1.z = o[6] + bb[6]; v1.w = o[7] + bb[7];
        int b = row >> 11;
        int s = row & (S_LEN - 1);
        int h = col0 >> 6;
        int d = col0 & 63;
        size_t base = (((size_t)b * NH + h) * S_LEN + s) * DH + d;
        *(float4*)&C[base]     = v0;
        *(float4*)&C[base + 4] = v1;
    }
}

// ---------------------------------------------------------------------------
// Output projection: out = g_o @ Wo + bo  (row-major)
// ---------------------------------------------------------------------------
__global__ __launch_bounds__(256, 2)
void gemm_out(const float* __restrict__ A, const float* __restrict__ W,
              const float* __restrict__ bias, float* __restrict__ C)
{
    __shared__ float As[16][132];
    __shared__ float Bs[16][132];

    const int tid = threadIdx.x;
    const int bm = blockIdx.x * 128;
    const int bn = blockIdx.y * 128;
    const int tx = tid & 15;
    const int ty = tid >> 4;

    ull acc[8][4] = {};

    for (int k0 = 0; k0 < DM; k0 += 16) {
        #pragma unroll
        for (int i = 0; i < 2; i++) {
            int lin = tid + i * 256;
            int r = lin >> 2, c4 = lin & 3;
            float4 v = *(const float4*)&A[(size_t)(bm + r) * DM + k0 + c4 * 4];
            As[c4 * 4 + 0][r] = v.x; As[c4 * 4 + 1][r] = v.y;
            As[c4 * 4 + 2][r] = v.z; As[c4 * 4 + 3][r] = v.w;
        }
        #pragma unroll
        for (int i = 0; i < 2; i++) {
            int lin = tid + i * 256;
            int r = lin >> 5, c4 = lin & 31;
            *(float4*)&Bs[r][c4 * 4] =
                *(const float4*)&W[(size_t)(k0 + r) * DM + bn + c4 * 4];
        }
        __syncthreads();

        #pragma unroll
        for (int kk = 0; kk < 16; kk++) {
            float a8[8];
            *(float4*)&a8[0] = *(const float4*)&As[kk][ty * 8];
            *(float4*)&a8[4] = *(const float4*)&As[kk][ty * 8 + 4];
            ull b0 = *(const ull*)&Bs[kk][tx * 8 + 0];
            ull b1 = *(const ull*)&Bs[kk][tx * 8 + 2];
            ull b2 = *(const ull*)&Bs[kk][tx * 8 + 4];
            ull b3 = *(const ull*)&Bs[kk][tx * 8 + 6];
            #pragma unroll
            for (int i = 0; i < 8; i++) {
                ull ap; PACK2(ap, a8[i]);
                FMA2(acc[i][0], ap, b0, acc[i][0]);
                FMA2(acc[i][1], ap, b1, acc[i][1]);
                FMA2(acc[i][2], ap, b2, acc[i][2]);
                FMA2(acc[i][3], ap, b3, acc[i][3]);
            }
        }
        __syncthreads();
    }

    float bb[8];
    *(float4*)&bb[0] = *(const float4*)&bias[bn + tx * 8];
    *(float4*)&bb[4] = *(const float4*)&bias[bn + tx * 8 + 4];

    #pragma unroll
    for (int i = 0; i < 8; i++) {
        int row = bm + ty * 8 + i;
        float o[8];
        #pragma unroll
        for (int p = 0; p < 4; p++) UNPACK2(o[2*p], o[2*p+1], acc[i][p]);
        float4 v0, v1;
        v0.x = o[0] + bb[0]; v0.y = o[1] + bb[1];
        v0.z = o[2] + bb[2]; v0.w = o[3] + bb[3];
        v1.x = o[4] + bb[4]; v1.y = o[5] + bb[5];
        v1.z = o[6] + bb[6]; v1.w = o[7] + bb[7];
        size_t base = (size_t)row * DM + bn + tx * 8;
        *(float4*)&C[base]     = v0;
        *(float4*)&C[base + 4] = v1;
    }
}

// ---------------------------------------------------------------------------
// Scores: attn[bh] = scale * q[bh] @ k[bh]^T, 128x128 tile, packed FFMA2.
// ---------------------------------------------------------------------------
__global__ __launch_bounds__(256, 2)
void scores_kernel(const float* __restrict__ q, const float* __restrict__ k,
                   float* __restrict__ attn, float scale)
{
    __shared__ float Qs[32][132];
    __shared__ float Ks[32][132];

    const int bh = blockIdx.z;
    const float* qb = q + (size_t)bh * S_LEN * DH;
    const float* kb = k + (size_t)bh * S_LEN * DH;
    float* ab = attn + (size_t)bh * S_LEN * S_LEN;

    const int tid = threadIdx.x;
    const int bm = blockIdx.y * 128;
    const int bn = blockIdx.x * 128;
    const int tx = tid & 15;
    const int ty = tid >> 4;

    ull acc[8][4] = {};

    for (int k0 = 0; k0 < DH; k0 += 32) {
        #pragma unroll
        for (int i = 0; i < 4; i++) {
            int lin = tid + i * 256;          // 0..1023
            int r = lin >> 3;                 // 0..127
            int c4 = lin & 7;                 // 0..7
            float4 vq = *(const float4*)&qb[(size_t)(bm + r) * DH + k0 + c4 * 4];
            float4 vk = *(const float4*)&kb[(size_t)(bn + r) * DH + k0 + c4 * 4];
            Qs[c4 * 4 + 0][r] = vq.x; Qs[c4 * 4 + 1][r] = vq.y;
            Qs[c4 * 4 + 2][r] = vq.z; Qs[c4 * 4 + 3][r] = vq.w;
            Ks[c4 * 4 + 0][r] = vk.x; Ks[c4 * 4 + 1][r] = vk.y;
            Ks[c4 * 4 + 2][r] = vk.z; Ks[c4 * 4 + 3][r] = vk.w;
        }
        __syncthreads();

        #pragma unroll
        for (int kk = 0; kk < 32; kk++) {
            float a8[8];
            *(float4*)&a8[0] = *(const float4*)&Qs[kk][ty * 8];
            *(float4*)&a8[4] = *(const float4*)&Qs[kk][ty * 8 + 4];
            ull b0 = *(const ull*)&Ks[kk][tx * 8 + 0];
            ull b1 = *(const ull*)&Ks[kk][tx * 8 + 2];
            ull b2 = *(const ull*)&Ks[kk][tx * 8 + 4];
            ull b3 = *(const ull*)&Ks[kk][tx * 8 + 6];
            #pragma unroll
            for (int i = 0; i < 8; i++) {
                ull ap; PACK2(ap, a8[i]);
                FMA2(acc[i][0], ap, b0, acc[i][0]);
                FMA2(acc[i][1], ap, b1, acc[i][1]);
                FMA2(acc[i][2], ap, b2, acc[i][2]);
                FMA2(acc[i][3], ap, b3, acc[i][3]);
            }
        }
        __syncthreads();
    }

    #pragma unroll
    for (int i = 0; i < 8; i++) {
        float o[8];
        #pragma unroll
        for (int p = 0; p < 4; p++) UNPACK2(o[2*p], o[2*p+1], acc[i][p]);
        size_t base = (size_t)(bm + ty * 8 + i) * S_LEN + bn + tx * 8;
        float4 v0, v1;
        v0.x = o[0] * scale; v0.y = o[1] * scale;
        v0.z = o[2] * scale; v0.w = o[3] * scale;
        v1.x = o[4] * scale; v1.y = o[5] * scale;
        v1.z = o[6] * scale; v1.w = o[7] * scale;
        *(float4*)&ab[base]     = v0;
        *(float4*)&ab[base + 4] = v1;
    }
}

// ---------------------------------------------------------------------------
// Row softmax over last dim (2048).
// ---------------------------------------------------------------------------
__global__ __launch_bounds__(256)
void softmax2048(float* __restrict__ attn)
{
    __shared__ float red[256];
    float* p = attn + (size_t)blockIdx.x * S_LEN;
    const int tid = threadIdx.x;

    float4 x0 = ((const float4*)p)[tid];
    float4 x1 = ((const float4*)p)[tid + 256];

    float m = fmaxf(fmaxf(fmaxf(x0.x, x0.y), fmaxf(x0.z, x0.w)),
                    fmaxf(fmaxf(x1.x, x1.y), fmaxf(x1.z, x1.w)));
    red[tid] = m;
    __syncthreads();
    #pragma unroll
    for (int s = 128; s > 0; s >>= 1) {
        if (tid < s) red[tid] = fmaxf(red[tid], red[tid + s]);
        __syncthreads();
    }
    m = red[0];
    __syncthreads();

    x0.x = __expf(x0.x - m); x0.y = __expf(x0.y - m);
    x0.z = __expf(x0.z - m); x0.w = __expf(x0.w - m);
    x1.x = __expf(x1.x - m); x1.y = __expf(x1.y - m);
    x1.z = __expf(x1.z - m); x1.w = __expf(x1.w - m);

    float sum = x0.x + x0.y + x0.z + x0.w + x1.x + x1.y + x1.z + x1.w;
    red[tid] = sum;
    __syncthreads();
    #pragma unroll
    for (int s = 128; s > 0; s >>= 1) {
        if (tid < s) red[tid] += red[tid + s];
        __syncthreads();
    }
    float inv = 1.0f / red[0];

    x0.x *= inv; x0.y *= inv; x0.z *= inv; x0.w *= inv;
    x1.x *= inv; x1.y *= inv; x1.z *= inv; x1.w *= inv;

    ((float4*)p)[tid] = x0;
    ((float4*)p)[tid + 256] = x1;
}

// ---------------------------------------------------------------------------
// AV: o[bh] = attn[bh][S,S] @ v[bh][S,DH] -> concat-head layout.
// Tile 128(m) x 64(n), 128 threads, 8x8 micro (packed), k-tile 32.
// ---------------------------------------------------------------------------
__global__ __launch_bounds__(128, 3)
void av_kernel(const float* __restrict__ attn, const float* __restrict__ v,
               float* __restrict__ o)
{
    __shared__ float Ps[32][132];   // [k][m]
    __shared__ float Vs[32][68];    // [k][n]

    const int bh = blockIdx.z;
    const int b = bh >> 4, h = bh & 15;
    const float* ab = attn + (size_t)bh * S_LEN * S_LEN;
    const float* vb = v + (size_t)bh * S_LEN * DH;

    const int tid = threadIdx.x;
    const int bm = blockIdx.x * 128;
    const int tx = tid & 7;         // 0..7  -> 64 cols
    const int ty = tid >> 3;        // 0..15 -> 128 rows

    ull acc[8][4] = {};

    for (int k0 = 0; k0 < S_LEN; k0 += 32) {
        #pragma unroll
        for (int i = 0; i < 8; i++) {
            int lin = tid + i * 128;          // 0..1023
            int r = lin >> 3;                 // 0..127
            int c4 = lin & 7;                 // 0..7
            float4 vp = *(const float4*)&ab[(size_t)(bm + r) * S_LEN + k0 + c4 * 4];
            Ps[c4 * 4 + 0][r] = vp.x; Ps[c4 * 4 + 1][r] = vp.y;
            Ps[c4 * 4 + 2][r] = vp.z; Ps[c4 * 4 + 3][r] = vp.w;
        }
        #pragma unroll
        for (int i = 0; i < 4; i++) {
            int lin = tid + i * 128;          // 0..511
            int r = lin >> 4;                 // 0..31
            int c4 = lin & 15;                // 0..15
            *(float4*)&Vs[r][c4 * 4] =
                *(const float4*)&vb[(size_t)(k0 + r) * DH + c4 * 4];
        }
        __syncthreads();

        #pragma unroll
        for (int kk = 0; kk < 32; kk++) {
            float a8[8];
            *(float4*)&a8[0] = *(const float4*)&Ps[kk][ty * 8];
            *(float4*)&a8[4] = *(const float4*)&Ps[kk][ty * 8 + 4];
            ull b0 = *(const ull*)&Vs[kk][tx * 8 + 0];
            ull b1 = *(const ull*)&Vs[kk][tx * 8 + 2];
            ull b2 = *(const ull*)&Vs[kk][tx * 8 + 4];
            ull b3 = *(const ull*)&Vs[kk][tx * 8 + 6];
            #pragma unroll
            for (int i = 0; i < 8; i++) {
                ull ap; PACK2(ap, a8[i]);
                FMA2(acc[i][0], ap, b0, acc[i][0]);
                FMA2(acc[i][1], ap, b1, acc[i][1]);
                FMA2(acc[i][2], ap, b2, acc[i][2]);
                FMA2(acc[i][3], ap, b3, acc[i][3]);
            }
        }
        __syncthreads();
    }

    #pragma unroll
    for (int i = 0; i < 8; i++) {
        int s = bm + ty * 8 + i;
        float oo[8];
        #pragma unroll
        for (int p = 0; p < 4; p++) UNPACK2(oo[2*p], oo[2*p+1], acc[i][p]);
        size_t base = ((size_t)b * S_LEN + s) * DM + h * DH + tx * 8;
        float4 v0, v1;
        v0.x = oo[0]; v0.y = oo[1]; v0.z = oo[2]; v0.w = oo[3];
        v1.x = oo[4]; v1.y = oo[5]; v1.z = oo[6]; v1.w = oo[7];
        *(float4*)&o[base]     = v0;
        *(float4*)&o[base + 4] = v1;
    }
}

extern "C" void kernel_launch(void* const* d_in, const int* in_sizes, int n_in,
                              void* d_out, int out_size)
{
    const float* Q  = (const float*)d_in[0];
    const float* K  = (const float*)d_in[1];
    const float* V  = (const float*)d_in[2];
    const float* Wq = (const float*)d_in[3];
    const float* bq = (const float*)d_in[4];
    const float* Wk = (const float*)d_in[5];
    const float* bk = (const float*)d_in[6];
    const float* Wv = (const float*)d_in[7];
    const float* bv = (const float*)d_in[8];
    const float* Wo = (const float*)d_in[9];
    const float* bo = (const float*)d_in[10];

    float* out  = (float*)d_out;                 // [B, S, DM]
    float* attn = out + OUT_ELEMS;               // [B, H, S, S]

    float *gq, *gk, *gv, *go;
    cudaGetSymbolAddress((void**)&gq, g_q);
    cudaGetSymbolAddress((void**)&gk, g_k);
    cudaGetSymbolAddress((void**)&gv, g_v);
    cudaGetSymbolAddress((void**)&go, g_o);

    dim3 blk(256);

    // Fused QKV projections (grid.z selects which)
    dim3 gqkv(M_ROWS / 128, DM / 128, 3);        // (32, 8, 3)
    proj_qkv<<<gqkv, blk>>>(Q, K, V, Wq, Wk, Wv, bq, bk, bv, gq, gk, gv);

    dim3 gsc(S_LEN / 128, S_LEN / 128, B_SZ * NH);   // (16, 16, 32)
    scores_kernel<<<gsc, blk>>>(gq, gk, attn, 0.125f);

    softmax2048<<<B_SZ * NH * S_LEN, 256>>>(attn);

    dim3 gav(S_LEN / 128, 1, B_SZ * NH);             // (16, 1, 32)
    av_kernel<<<gav, dim3(128)>>>(attn, gv, go);

    dim3 gout(M_ROWS / 128, DM / 128);               // (32, 8)
    gemm_out<<<gout, blk>>>(go, Wo, bo, out);
}

// round 5
// speedup vs baseline: 1.7665x; 1.7665x over previous
#include <cuda_runtime.h>
#include <cuda_bf16.h>
#include <cstdint>
#include <math.h>

#define B_SZ 2
#define S_LEN 2048
#define NH 16
#define DH 64
#define DM 1024
#define BH (B_SZ * NH)                 // 32
#define M_ROWS (B_SZ * S_LEN)          // 4096
#define OUT_ELEMS (B_SZ * S_LEN * DM)  // 4,194,304

// ===========================================================================
// Device scratch (allocation-free rule)
// ===========================================================================
__device__ uint32_t g_inP[3][M_ROWS * DM];  // packed (hi|lo<<16) bf16 of Q,K,V inputs
__device__ uint32_t g_wT[4][DM * DM];       // packed, transposed weights [N][K]
__device__ uint32_t g_qp[BH * S_LEN * DH];  // q packed [bh][s][dh]
__device__ uint32_t g_kp[BH * S_LEN * DH];  // k packed [bh][s][dh]
__device__ uint32_t g_vp[BH * DH * S_LEN];  // v packed TRANSPOSED [bh][dh][s]
__device__ uint32_t g_op[M_ROWS * DM];      // attn@v packed [m][dm]

// ===========================================================================
// Split-precision pack: fp32 -> (hi bf16 | lo bf16 << 16)
// ===========================================================================
__device__ __forceinline__ uint32_t pack_split(float x) {
    __nv_bfloat16 h = __float2bfloat16(x);
    __nv_bfloat16 l = __float2bfloat16(x - __bfloat162float(h));
    return (uint32_t)__bfloat16_as_ushort(h) | ((uint32_t)__bfloat16_as_ushort(l) << 16);
}

// ===========================================================================
// HMMA m16n8k16 bf16 (arch-agnostic PTX, runs on tensor pipe)
// A row-major frag {a0..a3}, B col-major frag {b0,b1}, fp32 accum in-place.
// ===========================================================================
__device__ __forceinline__ void mma16816(float* c, const uint32_t* a,
                                         uint32_t b0, uint32_t b1) {
    asm volatile(
        "mma.sync.aligned.m16n8k16.row.col.f32.bf16.bf16.f32 "
        "{%0,%1,%2,%3}, {%4,%5,%6,%7}, {%8,%9}, {%0,%1,%2,%3};"
        : "+f"(c[0]), "+f"(c[1]), "+f"(c[2]), "+f"(c[3])
        : "r"(a[0]), "r"(a[1]), "r"(a[2]), "r"(a[3]), "r"(b0), "r"(b1));
}

// ===========================================================================
// Smem plane fill. Layout: [row][k/2] u32 (bf16 pair along k), row stride
// KSTR = KC/2 + 4 u32 -> bank = (4*row + kidx) % 32, conflict-free.
// Source: packed u32 (hi|lo per element).
// ===========================================================================
template <int ROWS, int KC>
__device__ __forceinline__ void fill_planes(uint32_t* __restrict__ hi,
                                            uint32_t* __restrict__ lo,
                                            const uint32_t* __restrict__ src,
                                            size_t stride, int tid) {
    constexpr int KSTR = KC / 2 + 4;
    constexpr int QUADS = KC / 4;
    #pragma unroll
    for (int i = 0; i < ROWS * QUADS / 256; i++) {
        int lin = tid + i * 256;
        int r = lin / QUADS, q = lin % QUADS, k = q * 4;
        uint4 p = *(const uint4*)(src + (size_t)r * stride + k);
        uint32_t h01 = (p.x & 0xFFFFu) | ((p.y & 0xFFFFu) << 16);
        uint32_t h23 = (p.z & 0xFFFFu) | ((p.w & 0xFFFFu) << 16);
        uint32_t l01 = (p.x >> 16) | (p.y & 0xFFFF0000u);
        uint32_t l23 = (p.z >> 16) | (p.w & 0xFFFF0000u);
        int idx = r * KSTR + k / 2;
        *(uint2*)(hi + idx) = make_uint2(h01, h23);
        *(uint2*)(lo + idx) = make_uint2(l01, l23);
    }
}

// Same, from fp32 source (split on the fly)
template <int ROWS, int KC>
__device__ __forceinline__ void fill_f32_planes(uint32_t* __restrict__ hi,
                                                uint32_t* __restrict__ lo,
                                                const float* __restrict__ src,
                                                size_t stride, int tid) {
    constexpr int KSTR = KC / 2 + 4;
    constexpr int QUADS = KC / 4;
    #pragma unroll
    for (int i = 0; i < ROWS * QUADS / 256; i++) {
        int lin = tid + i * 256;
        int r = lin / QUADS, q = lin % QUADS, k = q * 4;
        float4 f = *(const float4*)(src + (size_t)r * stride + k);
        uint32_t p0 = pack_split(f.x), p1 = pack_split(f.y);
        uint32_t p2 = pack_split(f.z), p3 = pack_split(f.w);
        uint32_t h01 = (p0 & 0xFFFFu) | ((p1 & 0xFFFFu) << 16);
        uint32_t h23 = (p2 & 0xFFFFu) | ((p3 & 0xFFFFu) << 16);
        uint32_t l01 = (p0 >> 16) | (p1 & 0xFFFF0000u);
        uint32_t l23 = (p2 >> 16) | (p3 & 0xFFFF0000u);
        int idx = r * KSTR + k / 2;
        *(uint2*)(hi + idx) = make_uint2(h01, h23);
        *(uint2*)(lo + idx) = make_uint2(l01, l23);
    }
}

// ===========================================================================
// Warp-level MMA over one smem chunk. WM x WN m16n8 tiles per warp.
// acc layout: acc[mt][nt][4] (c0:{r,c},c1:{r,c+1},c2:{r+8,c},c3:{r+8,c+1})
// ===========================================================================
template <int WM, int WN, int KC>
__device__ __forceinline__ void mma_chunk(float acc[WM][WN][4],
                                          const uint32_t* __restrict__ Ah,
                                          const uint32_t* __restrict__ Al,
                                          const uint32_t* __restrict__ Bh,
                                          const uint32_t* __restrict__ Bl,
                                          int warp_m, int warp_n, int lane) {
    constexpr int KSTR = KC / 2 + 4;
    const int lr = lane >> 2;   // 0..7
    const int lk = lane & 3;    // 0..3
    #pragma unroll
    for (int ks = 0; ks < KC / 16; ks++) {
        int kb = ks * 8 + lk;
        uint32_t ah[WM][4], al[WM][4];
        #pragma unroll
        for (int mt = 0; mt < WM; mt++) {
            int base = (warp_m + mt * 16 + lr) * KSTR + kb;
            ah[mt][0] = Ah[base];            ah[mt][1] = Ah[base + 8 * KSTR];
            ah[mt][2] = Ah[base + 4];        ah[mt][3] = Ah[base + 8 * KSTR + 4];
            al[mt][0] = Al[base];            al[mt][1] = Al[base + 8 * KSTR];
            al[mt][2] = Al[base + 4];        al[mt][3] = Al[base + 8 * KSTR + 4];
        }
        #pragma unroll
        for (int nt = 0; nt < WN; nt++) {
            int cb = (warp_n + nt * 8 + lr) * KSTR + kb;
            uint32_t bh0 = Bh[cb], bh1 = Bh[cb + 4];
            uint32_t bl0 = Bl[cb], bl1 = Bl[cb + 4];
            #pragma unroll
            for (int mt = 0; mt < WM; mt++) {
                mma16816(acc[mt][nt], ah[mt], bh0, bh1);
                mma16816(acc[mt][nt], ah[mt], bl0, bl1);
                mma16816(acc[mt][nt], al[mt], bh0, bh1);
            }
        }
    }
}

// ===========================================================================
// Conversion kernels
// ===========================================================================
__global__ __launch_bounds__(256)
void convert_in(const float* __restrict__ Q, const float* __restrict__ K,
                const float* __restrict__ V, uint32_t* __restrict__ dst)
{
    const float* src = (blockIdx.y == 0) ? Q : (blockIdx.y == 1) ? K : V;
    uint32_t* d = dst + (size_t)blockIdx.y * (M_ROWS * DM);
    size_t idx = ((size_t)blockIdx.x * 256 + threadIdx.x) * 4;
    float4 f = *(const float4*)(src + idx);
    uint4 o;
    o.x = pack_split(f.x); o.y = pack_split(f.y);
    o.z = pack_split(f.z); o.w = pack_split(f.w);
    *(uint4*)(d + idx) = o;
}

__global__ __launch_bounds__(256)
void convert_w(const float* __restrict__ Wq, const float* __restrict__ Wk,
               const float* __restrict__ Wv, const float* __restrict__ Wo,
               uint32_t* __restrict__ dst)
{
    __shared__ float sm[64][65];
    const float* W = (blockIdx.z == 0) ? Wq : (blockIdx.z == 1) ? Wk :
                     (blockIdx.z == 2) ? Wv : Wo;
    uint32_t* d = dst + (size_t)blockIdx.z * (DM * DM);
    const int k0 = blockIdx.x * 64;
    const int n0 = blockIdx.y * 64;
    const int tid = threadIdx.x;

    #pragma unroll
    for (int i = 0; i < 4; i++) {
        int lin = tid + i * 256;
        int r = lin >> 4, q = lin & 15;
        float4 f = *(const float4*)(W + (size_t)(k0 + r) * DM + n0 + q * 4);
        sm[r][q * 4 + 0] = f.x; sm[r][q * 4 + 1] = f.y;
        sm[r][q * 4 + 2] = f.z; sm[r][q * 4 + 3] = f.w;
    }
    __syncthreads();
    #pragma unroll
    for (int i = 0; i < 4; i++) {
        int lin = tid + i * 256;
        int r = lin >> 4, q = lin & 15;   // r = n offset, q = k quad
        uint4 o;
        o.x = pack_split(sm[q * 4 + 0][r]);
        o.y = pack_split(sm[q * 4 + 1][r]);
        o.z = pack_split(sm[q * 4 + 2][r]);
        o.w = pack_split(sm[q * 4 + 3][r]);
        *(uint4*)(d + (size_t)(n0 + r) * DM + k0 + q * 4) = o;
    }
}

// ===========================================================================
// QKV projection: 128x128 CTA tile, 8 warps (2m x 4n), warp 64x32, K=1024.
// z picks which projection. Outputs: q/k packed head-split, v packed transposed.
// ===========================================================================
__global__ __launch_bounds__(256)
void proj_mma(const uint32_t* __restrict__ inP, const uint32_t* __restrict__ wT,
              const float* __restrict__ bq, const float* __restrict__ bk,
              const float* __restrict__ bv,
              uint32_t* __restrict__ qp, uint32_t* __restrict__ kp,
              uint32_t* __restrict__ vp)
{
    constexpr int KC = 128, KSTR = KC / 2 + 4;
    extern __shared__ uint32_t sm[];
    uint32_t* Ah = sm;
    uint32_t* Al = Ah + 128 * KSTR;
    uint32_t* Bh = Al + 128 * KSTR;
    uint32_t* Bl = Bh + 128 * KSTR;

    const int z = blockIdx.z;
    const uint32_t* A = inP + (size_t)z * (M_ROWS * DM);
    const uint32_t* W = wT + (size_t)z * (DM * DM);
    const float* bias = (z == 0) ? bq : (z == 1) ? bk : bv;

    const int tid = threadIdx.x;
    const int wid = tid >> 5, lane = tid & 31;
    const int bm = blockIdx.x * 128;
    const int bn = blockIdx.y * 128;
    const int warp_m = (wid >> 2) * 64;
    const int warp_n = (wid & 3) * 32;

    float acc[4][4][4] = {};

    #pragma unroll 1
    for (int c = 0; c < DM / KC; c++) {
        fill_planes<128, KC>(Ah, Al, A + (size_t)bm * DM + c * KC, DM, tid);
        fill_planes<128, KC>(Bh, Bl, W + (size_t)bn * DM + c * KC, DM, tid);
        __syncthreads();
        mma_chunk<4, 4, KC>(acc, Ah, Al, Bh, Bl, warp_m, warp_n, lane);
        __syncthreads();
    }

    const int lr = lane >> 2, lc = (lane & 3) * 2;
    #pragma unroll
    for (int mt = 0; mt < 4; mt++) {
        #pragma unroll
        for (int nt = 0; nt < 4; nt++) {
            int col = bn + warp_n + nt * 8 + lc;
            float b0 = bias[col], b1 = bias[col + 1];
            int h = col >> 6, dh = col & 63;
            #pragma unroll
            for (int half = 0; half < 2; half++) {
                int r = bm + warp_m + mt * 16 + lr + half * 8;
                float v0 = acc[mt][nt][half * 2 + 0] + b0;
                float v1 = acc[mt][nt][half * 2 + 1] + b1;
                int b = r >> 11, s = r & (S_LEN - 1);
                int bh = b * NH + h;
                if (z == 2) {
                    vp[((size_t)bh * DH + dh) * S_LEN + s]     = pack_split(v0);
                    vp[((size_t)bh * DH + dh + 1) * S_LEN + s] = pack_split(v1);
                } else {
                    uint32_t* dst = (z == 0) ? qp : kp;
                    size_t base = ((size_t)bh * S_LEN + s) * DH + dh;
                    *(uint2*)(dst + base) = make_uint2(pack_split(v0), pack_split(v1));
                }
            }
        }
    }
}

// ===========================================================================
// Scores: attn = scale * q @ k^T per bh. 128x128 tile, K=64 single chunk.
// ===========================================================================
__global__ __launch_bounds__(256)
void scores_mma(const uint32_t* __restrict__ qp, const uint32_t* __restrict__ kp,
                float* __restrict__ attn, float scale)
{
    constexpr int KC = 64, KSTR = KC / 2 + 4;
    extern __shared__ uint32_t sm[];
    uint32_t* Ah = sm;
    uint32_t* Al = Ah + 128 * KSTR;
    uint32_t* Bh = Al + 128 * KSTR;
    uint32_t* Bl = Bh + 128 * KSTR;

    const int bh = blockIdx.z;
    const int tid = threadIdx.x;
    const int wid = tid >> 5, lane = tid & 31;
    const int bm = blockIdx.y * 128;
    const int bn = blockIdx.x * 128;
    const int warp_m = (wid >> 2) * 64;
    const int warp_n = (wid & 3) * 32;
    const uint32_t* qb = qp + ((size_t)bh * S_LEN + bm) * DH;
    const uint32_t* kb = kp + ((size_t)bh * S_LEN + bn) * DH;
    float* ab = attn + (size_t)bh * S_LEN * S_LEN;

    float acc[4][4][4] = {};

    fill_planes<128, KC>(Ah, Al, qb, DH, tid);
    fill_planes<128, KC>(Bh, Bl, kb, DH, tid);
    __syncthreads();
    mma_chunk<4, 4, KC>(acc, Ah, Al, Bh, Bl, warp_m, warp_n, lane);

    const int lr = lane >> 2, lc = (lane & 3) * 2;
    #pragma unroll
    for (int mt = 0; mt < 4; mt++) {
        #pragma unroll
        for (int nt = 0; nt < 4; nt++) {
            int col = bn + warp_n + nt * 8 + lc;
            #pragma unroll
            for (int half = 0; half < 2; half++) {
                int r = bm + warp_m + mt * 16 + lr + half * 8;
                float2 o;
                o.x = acc[mt][nt][half * 2 + 0] * scale;
                o.y = acc[mt][nt][half * 2 + 1] * scale;
                *(float2*)(ab + (size_t)r * S_LEN + col) = o;
            }
        }
    }
}

// ===========================================================================
// Row softmax over last dim (2048)
// ===========================================================================
__global__ __launch_bounds__(256)
void softmax2048(float* __restrict__ attn)
{
    __shared__ float red[256];
    float* p = attn + (size_t)blockIdx.x * S_LEN;
    const int tid = threadIdx.x;

    float4 x0 = ((const float4*)p)[tid];
    float4 x1 = ((const float4*)p)[tid + 256];

    float m = fmaxf(fmaxf(fmaxf(x0.x, x0.y), fmaxf(x0.z, x0.w)),
                    fmaxf(fmaxf(x1.x, x1.y), fmaxf(x1.z, x1.w)));
    red[tid] = m;
    __syncthreads();
    #pragma unroll
    for (int s = 128; s > 0; s >>= 1) {
        if (tid < s) red[tid] = fmaxf(red[tid], red[tid + s]);
        __syncthreads();
    }
    m = red[0];
    __syncthreads();

    x0.x = __expf(x0.x - m); x0.y = __expf(x0.y - m);
    x0.z = __expf(x0.z - m); x0.w = __expf(x0.w - m);
    x1.x = __expf(x1.x - m); x1.y = __expf(x1.y - m);
    x1.z = __expf(x1.z - m); x1.w = __expf(x1.w - m);

    float sum = x0.x + x0.y + x0.z + x0.w + x1.x + x1.y + x1.z + x1.w;
    red[tid] = sum;
    __syncthreads();
    #pragma unroll
    for (int s = 128; s > 0; s >>= 1) {
        if (tid < s) red[tid] += red[tid + s];
        __syncthreads();
    }
    float inv = 1.0f / red[0];

    x0.x *= inv; x0.y *= inv; x0.z *= inv; x0.w *= inv;
    x1.x *= inv; x1.y *= inv; x1.z *= inv; x1.w *= inv;

    ((float4*)p)[tid] = x0;
    ((float4*)p)[tid + 256] = x1;
}

// ===========================================================================
// AV: o = attn @ v per bh. 128(m) x 64(n) tile, 8 warps (4m x 2n), warp 32x32.
// A = fp32 attn (split on fill), B = v transposed packed [dh][s] (K-major).
// ===========================================================================
__global__ __launch_bounds__(256)
void av_mma(const float* __restrict__ attn, const uint32_t* __restrict__ vp,
            uint32_t* __restrict__ op)
{
    constexpr int KC = 128, KSTR = KC / 2 + 4;
    extern __shared__ uint32_t sm[];
    uint32_t* Ah = sm;
    uint32_t* Al = Ah + 128 * KSTR;
    uint32_t* Bh = Al + 128 * KSTR;
    uint32_t* Bl = Bh + 64 * KSTR;

    const int bh = blockIdx.z;
    const int bb = bh >> 4, h = bh & 15;
    const int tid = threadIdx.x;
    const int wid = tid >> 5, lane = tid & 31;
    const int bm = blockIdx.x * 128;
    const int warp_m = (wid >> 1) * 32;
    const int warp_n = (wid & 1) * 32;
    const float* ab = attn + ((size_t)bh * S_LEN + bm) * S_LEN;
    const uint32_t* vb = vp + (size_t)bh * DH * S_LEN;

    float acc[2][4][4] = {};

    #pragma unroll 1
    for (int c = 0; c < S_LEN / KC; c++) {
        fill_f32_planes<128, KC>(Ah, Al, ab + c * KC, S_LEN, tid);
        fill_planes<64, KC>(Bh, Bl, vb + c * KC, S_LEN, tid);
        __syncthreads();
        mma_chunk<2, 4, KC>(acc, Ah, Al, Bh, Bl, warp_m, warp_n, lane);
        __syncthreads();
    }

    const int lr = lane >> 2, lc = (lane & 3) * 2;
    #pragma unroll
    for (int mt = 0; mt < 2; mt++) {
        #pragma unroll
        for (int nt = 0; nt < 4; nt++) {
            int col = warp_n + nt * 8 + lc;     // 0..63 (= dh)
            #pragma unroll
            for (int half = 0; half < 2; half++) {
                int s = bm + warp_m + mt * 16 + lr + half * 8;
                float v0 = acc[mt][nt][half * 2 + 0];
                float v1 = acc[mt][nt][half * 2 + 1];
                size_t base = ((size_t)bb * S_LEN + s) * DM + h * DH + col;
                *(uint2*)(op + base) = make_uint2(pack_split(v0), pack_split(v1));
            }
        }
    }
}

// ===========================================================================
// Output projection: out = op @ WoT + bo (fp32 out)
// ===========================================================================
__global__ __launch_bounds__(256)
void out_mma(const uint32_t* __restrict__ op, const uint32_t* __restrict__ woT,
             const float* __restrict__ bo, float* __restrict__ out)
{
    constexpr int KC = 128, KSTR = KC / 2 + 4;
    extern __shared__ uint32_t sm[];
    uint32_t* Ah = sm;
    uint32_t* Al = Ah + 128 * KSTR;
    uint32_t* Bh = Al + 128 * KSTR;
    uint32_t* Bl = Bh + 128 * KSTR;

    const int tid = threadIdx.x;
    const int wid = tid >> 5, lane = tid & 31;
    const int bm = blockIdx.x * 128;
    const int bn = blockIdx.y * 128;
    const int warp_m = (wid >> 2) * 64;
    const int warp_n = (wid & 3) * 32;

    float acc[4][4][4] = {};

    #pragma unroll 1
    for (int c = 0; c < DM / KC; c++) {
        fill_planes<128, KC>(Ah, Al, op + (size_t)bm * DM + c * KC, DM, tid);
        fill_planes<128, KC>(Bh, Bl, woT + (size_t)bn * DM + c * KC, DM, tid);
        __syncthreads();
        mma_chunk<4, 4, KC>(acc, Ah, Al, Bh, Bl, warp_m, warp_n, lane);
        __syncthreads();
    }

    const int lr = lane >> 2, lc = (lane & 3) * 2;
    #pragma unroll
    for (int mt = 0; mt < 4; mt++) {
        #pragma unroll
        for (int nt = 0; nt < 4; nt++) {
            int col = bn + warp_n + nt * 8 + lc;
            float b0 = bo[col], b1 = bo[col + 1];
            #pragma unroll
            for (int half = 0; half < 2; half++) {
                int r = bm + warp_m + mt * 16 + lr + half * 8;
                float2 o;
                o.x = acc[mt][nt][half * 2 + 0] + b0;
                o.y = acc[mt][nt][half * 2 + 1] + b1;
                *(float2*)(out + (size_t)r * DM + col) = o;
            }
        }
    }
}

// ===========================================================================
// Launch
// ===========================================================================
extern "C" void kernel_launch(void* const* d_in, const int* in_sizes, int n_in,
                              void* d_out, int out_size)
{
    const float* Q  = (const float*)d_in[0];
    const float* K  = (const float*)d_in[1];
    const float* V  = (const float*)d_in[2];
    const float* Wq = (const float*)d_in[3];
    const float* bq = (const float*)d_in[4];
    const float* Wk = (const float*)d_in[5];
    const float* bk = (const float*)d_in[6];
    const float* Wv = (const float*)d_in[7];
    const float* bv = (const float*)d_in[8];
    const float* Wo = (const float*)d_in[9];
    const float* bo = (const float*)d_in[10];

    float* out  = (float*)d_out;
    float* attn = out + OUT_ELEMS;

    uint32_t *inP, *wT, *qp, *kp, *vp, *op;
    cudaGetSymbolAddress((void**)&inP, g_inP);
    cudaGetSymbolAddress((void**)&wT,  g_wT);
    cudaGetSymbolAddress((void**)&qp,  g_qp);
    cudaGetSymbolAddress((void**)&kp,  g_kp);
    cudaGetSymbolAddress((void**)&vp,  g_vp);
    cudaGetSymbolAddress((void**)&op,  g_op);

    // smem sizes (bytes)
    const int KSTR128 = 128 / 2 + 4;                       // 68
    const int KSTR64  = 64 / 2 + 4;                        // 36
    const int SM_PROJ = 4 * 128 * KSTR128 * 4;             // 139,264
    const int SM_SC   = 4 * 128 * KSTR64 * 4;              //  73,728
    const int SM_AV   = (2 * 128 + 2 * 64) * KSTR128 * 4;  // 104,448
    cudaFuncSetAttribute(proj_mma, cudaFuncAttributeMaxDynamicSharedMemorySize, SM_PROJ);
    cudaFuncSetAttribute(out_mma, cudaFuncAttributeMaxDynamicSharedMemorySize, SM_PROJ);
    cudaFuncSetAttribute(scores_mma, cudaFuncAttributeMaxDynamicSharedMemorySize, SM_SC);
    cudaFuncSetAttribute(av_mma, cudaFuncAttributeMaxDynamicSharedMemorySize, SM_AV);

    // 1. convert inputs + weights
    convert_in<<<dim3(M_ROWS * DM / 4 / 256, 3), 256>>>(Q, K, V, inP);
    convert_w<<<dim3(DM / 64, DM / 64, 4), 256>>>(Wq, Wk, Wv, Wo, wT);

    // 2. projections
    proj_mma<<<dim3(M_ROWS / 128, DM / 128, 3), 256, SM_PROJ>>>(
        inP, wT, bq, bk, bv, qp, kp, vp);

    // 3. scores
    scores_mma<<<dim3(S_LEN / 128, S_LEN / 128, BH), 256, SM_SC>>>(
        qp, kp, attn, 0.125f);

    // 4. softmax
    softmax2048<<<BH * S_LEN, 256>>>(attn);

    // 5. attn @ v
    av_mma<<<dim3(S_LEN / 128, 1, BH), 256, SM_AV>>>(attn, vp, op);

    // 6. output projection
    out_mma<<<dim3(M_ROWS / 128, DM / 128), 256, SM_PROJ>>>(
        op, wT + 3 * (size_t)(DM * DM), bo, out);
}

// round 6
// speedup vs baseline: 1.8210x; 1.0309x over previous
#include <cuda_runtime.h>
#include <cuda_bf16.h>
#include <cstdint>
#include <math.h>

#define B_SZ 2
#define S_LEN 2048
#define NH 16
#define DH 64
#define DM 1024
#define BH (B_SZ * NH)                 // 32
#define M_ROWS (B_SZ * S_LEN)          // 4096
#define OUT_ELEMS (B_SZ * S_LEN * DM)  // 4,194,304

typedef unsigned short u16;

// ===========================================================================
// Device scratch (allocation-free rule) — separate hi/lo bf16 planes
// ===========================================================================
__device__ __align__(16) u16 g_inH[3][M_ROWS * DM];
__device__ __align__(16) u16 g_inL[3][M_ROWS * DM];
__device__ __align__(16) u16 g_wH[4][DM * DM];     // transposed [N][K]
__device__ __align__(16) u16 g_wL[4][DM * DM];
__device__ __align__(16) u16 g_qH[BH * S_LEN * DH];
__device__ __align__(16) u16 g_qL[BH * S_LEN * DH];
__device__ __align__(16) u16 g_kH[BH * S_LEN * DH];
__device__ __align__(16) u16 g_kL[BH * S_LEN * DH];
__device__ __align__(16) u16 g_vH[BH * DH * S_LEN];  // transposed [bh][dh][s]
__device__ __align__(16) u16 g_vL[BH * DH * S_LEN];
__device__ __align__(16) u16 g_oH[M_ROWS * DM];
__device__ __align__(16) u16 g_oL[M_ROWS * DM];
__device__ __align__(16) float2 g_stats[BH * S_LEN * 32];  // (m, sumexp) per 64-col tile
__device__ __align__(16) float2 g_row[BH * S_LEN];         // (M, 1/S) per row

// ===========================================================================
// Helpers
// ===========================================================================
__device__ __forceinline__ uint32_t pack_split(float x) {
    __nv_bfloat16 h = __float2bfloat16(x);
    __nv_bfloat16 l = __float2bfloat16(x - __bfloat162float(h));
    return (uint32_t)__bfloat16_as_ushort(h) | ((uint32_t)__bfloat16_as_ushort(l) << 16);
}

__device__ __forceinline__ uint32_t smem_u32(const void* p) {
    uint32_t a;
    asm("{ .reg .u64 t; cvta.to.shared.u64 t, %1; cvt.u32.u64 %0, t; }"
        : "=r"(a) : "l"(p));
    return a;
}

#define CPA16(s, g) \
    asm volatile("cp.async.cg.shared.global [%0], [%1], 16;" :: "r"(s), "l"(g))
#define CPC() asm volatile("cp.async.commit_group;" ::: "memory")
#define CPW(n) asm volatile("cp.async.wait_group %0;" :: "n"(n) : "memory")

__device__ __forceinline__ void mma16816(float* c, const uint32_t* a,
                                         uint32_t b0, uint32_t b1) {
    asm volatile(
        "mma.sync.aligned.m16n8k16.row.col.f32.bf16.bf16.f32 "
        "{%0,%1,%2,%3}, {%4,%5,%6,%7}, {%8,%9}, {%0,%1,%2,%3};"
        : "+f"(c[0]), "+f"(c[1]), "+f"(c[2]), "+f"(c[3])
        : "r"(a[0]), "r"(a[1]), "r"(a[2]), "r"(a[3]), "r"(b0), "r"(b1));
}

// ===========================================================================
// cp.async fill: ROWS x KC bf16 plane pair into smem (row stride KC/2+4 u32)
// ===========================================================================
template <int ROWS, int KC>
__device__ __forceinline__ void fill_async(uint32_t saH, uint32_t saL,
                                           const u16* __restrict__ gh,
                                           const u16* __restrict__ gl,
                                           size_t stride, int tid) {
    constexpr int SEGS = KC * 2 / 16;          // 16B segments per row
    constexpr int SSTR = (KC / 2 + 4) * 4;     // smem row stride bytes
    #pragma unroll
    for (int i = 0; i < ROWS * SEGS / 256; i++) {
        int lin = tid + i * 256;
        int r = lin / SEGS, s = lin % SEGS;
        uint32_t so = r * SSTR + s * 16;
        const char* gH = (const char*)(gh + (size_t)r * stride) + s * 16;
        const char* gL = (const char*)(gl + (size_t)r * stride) + s * 16;
        CPA16(saH + so, gH);
        CPA16(saL + so, gL);
    }
}

// Manual fill from u16 planes (for AV's B operand)
template <int ROWS, int KC>
__device__ __forceinline__ void fill_u16(uint32_t* __restrict__ hi,
                                         uint32_t* __restrict__ lo,
                                         const u16* __restrict__ gh,
                                         const u16* __restrict__ gl,
                                         size_t stride, int tid) {
    constexpr int SEGS = KC / 8;               // uint4 = 8 u16 per segment
    constexpr int KSTR = KC / 2 + 4;
    #pragma unroll
    for (int i = 0; i < ROWS * SEGS / 256; i++) {
        int lin = tid + i * 256;
        int r = lin / SEGS, s = lin % SEGS, k = s * 8;
        uint4 h = *(const uint4*)(gh + (size_t)r * stride + k);
        uint4 l = *(const uint4*)(gl + (size_t)r * stride + k);
        *(uint4*)(hi + r * KSTR + k / 2) = h;
        *(uint4*)(lo + r * KSTR + k / 2) = l;
    }
}

// AV A-fill: read raw scaled scores, apply softmax (exp(x-M)*invS), write
// normalized value back to attn, split into bf16 planes.
template <int ROWS, int KC>
__device__ __forceinline__ void fill_softmax(uint32_t* __restrict__ hi,
                                             uint32_t* __restrict__ lo,
                                             float* __restrict__ src,
                                             size_t stride,
                                             const float2* __restrict__ rowstat,
                                             int tid) {
    constexpr int KSTR = KC / 2 + 4;
    constexpr int QUADS = KC / 4;
    #pragma unroll
    for (int i = 0; i < ROWS * QUADS / 256; i++) {
        int lin = tid + i * 256;
        int r = lin / QUADS, q = lin % QUADS, k = q * 4;
        float2 st = rowstat[r];                 // (M, 1/S)
        float* p = src + (size_t)r * stride + k;
        float4 f = *(const float4*)p;
        f.x = __expf(f.x - st.x) * st.y;
        f.y = __expf(f.y - st.x) * st.y;
        f.z = __expf(f.z - st.x) * st.y;
        f.w = __expf(f.w - st.x) * st.y;
        *(float4*)p = f;                        // normalized attn (final output)
        uint32_t p0 = pack_split(f.x), p1 = pack_split(f.y);
        uint32_t p2 = pack_split(f.z), p3 = pack_split(f.w);
        int idx = r * KSTR + k / 2;
        *(uint2*)(hi + idx) = make_uint2((p0 & 0xFFFFu) | ((p1 & 0xFFFFu) << 16),
                                         (p2 & 0xFFFFu) | ((p3 & 0xFFFFu) << 16));
        *(uint2*)(lo + idx) = make_uint2((p0 >> 16) | (p1 & 0xFFFF0000u),
                                         (p2 >> 16) | (p3 & 0xFFFF0000u));
    }
}

// ===========================================================================
// Warp MMA over one chunk. acc[mt][nt][4]
// ===========================================================================
template <int WM, int WN, int KC>
__device__ __forceinline__ void mma_chunk(float acc[WM][WN][4],
                                          const uint32_t* __restrict__ Ah,
                                          const uint32_t* __restrict__ Al,
                                          const uint32_t* __restrict__ Bh,
                                          const uint32_t* __restrict__ Bl,
                                          int warp_m, int warp_n, int lane) {
    constexpr int KSTR = KC / 2 + 4;
    const int lr = lane >> 2;
    const int lk = lane & 3;
    #pragma unroll
    for (int ks = 0; ks < KC / 16; ks++) {
        int kb = ks * 8 + lk;
        uint32_t ah[WM][4], al[WM][4];
        #pragma unroll
        for (int mt = 0; mt < WM; mt++) {
            int base = (warp_m + mt * 16 + lr) * KSTR + kb;
            ah[mt][0] = Ah[base];     ah[mt][1] = Ah[base + 8 * KSTR];
            ah[mt][2] = Ah[base + 4]; ah[mt][3] = Ah[base + 8 * KSTR + 4];
            al[mt][0] = Al[base];     al[mt][1] = Al[base + 8 * KSTR];
            al[mt][2] = Al[base + 4]; al[mt][3] = Al[base + 8 * KSTR + 4];
        }
        #pragma unroll
        for (int nt = 0; nt < WN; nt++) {
            int cb = (warp_n + nt * 8 + lr) * KSTR + kb;
            uint32_t bh0 = Bh[cb], bh1 = Bh[cb + 4];
            uint32_t bl0 = Bl[cb], bl1 = Bl[cb + 4];
            #pragma unroll
            for (int mt = 0; mt < WM; mt++) {
                mma16816(acc[mt][nt], ah[mt], bh0, bh1);
                mma16816(acc[mt][nt], ah[mt], bl0, bl1);
                mma16816(acc[mt][nt], al[mt], bh0, bh1);
            }
        }
    }
}

// ===========================================================================
// Conversions
// ===========================================================================
__global__ __launch_bounds__(256)
void convert_in(const float* __restrict__ Q, const float* __restrict__ K,
                const float* __restrict__ V, u16* __restrict__ dh,
                u16* __restrict__ dl)
{
    const float* src = (blockIdx.y == 0) ? Q : (blockIdx.y == 1) ? K : V;
    u16* oh = dh + (size_t)blockIdx.y * (M_ROWS * DM);
    u16* ol = dl + (size_t)blockIdx.y * (M_ROWS * DM);
    size_t idx = ((size_t)blockIdx.x * 256 + threadIdx.x) * 8;
    float4 f0 = *(const float4*)(src + idx);
    float4 f1 = *(const float4*)(src + idx + 4);
    uint32_t p[8];
    p[0] = pack_split(f0.x); p[1] = pack_split(f0.y);
    p[2] = pack_split(f0.z); p[3] = pack_split(f0.w);
    p[4] = pack_split(f1.x); p[5] = pack_split(f1.y);
    p[6] = pack_split(f1.z); p[7] = pack_split(f1.w);
    uint4 hv, lv;
    hv.x = (p[0] & 0xFFFFu) | ((p[1] & 0xFFFFu) << 16);
    hv.y = (p[2] & 0xFFFFu) | ((p[3] & 0xFFFFu) << 16);
    hv.z = (p[4] & 0xFFFFu) | ((p[5] & 0xFFFFu) << 16);
    hv.w = (p[6] & 0xFFFFu) | ((p[7] & 0xFFFFu) << 16);
    lv.x = (p[0] >> 16) | (p[1] & 0xFFFF0000u);
    lv.y = (p[2] >> 16) | (p[3] & 0xFFFF0000u);
    lv.z = (p[4] >> 16) | (p[5] & 0xFFFF0000u);
    lv.w = (p[6] >> 16) | (p[7] & 0xFFFF0000u);
    *(uint4*)(oh + idx) = hv;
    *(uint4*)(ol + idx) = lv;
}

__global__ __launch_bounds__(256)
void convert_w(const float* __restrict__ Wq, const float* __restrict__ Wk,
               const float* __restrict__ Wv, const float* __restrict__ Wo,
               u16* __restrict__ dh, u16* __restrict__ dl)
{
    __shared__ float sm[64][65];
    const float* W = (blockIdx.z == 0) ? Wq : (blockIdx.z == 1) ? Wk :
                     (blockIdx.z == 2) ? Wv : Wo;
    u16* oh = dh + (size_t)blockIdx.z * (DM * DM);
    u16* ol = dl + (size_t)blockIdx.z * (DM * DM);
    const int k0 = blockIdx.x * 64;
    const int n0 = blockIdx.y * 64;
    const int tid = threadIdx.x;

    #pragma unroll
    for (int i = 0; i < 4; i++) {
        int lin = tid + i * 256;
        int r = lin >> 4, q = lin & 15;
        float4 f = *(const float4*)(W + (size_t)(k0 + r) * DM + n0 + q * 4);
        sm[r][q * 4 + 0] = f.x; sm[r][q * 4 + 1] = f.y;
        sm[r][q * 4 + 2] = f.z; sm[r][q * 4 + 3] = f.w;
    }
    __syncthreads();
    #pragma unroll
    for (int i = 0; i < 4; i++) {
        int lin = tid + i * 256;
        int r = lin >> 4, q = lin & 15;       // r = n offset, q = k quad
        uint32_t p0 = pack_split(sm[q * 4 + 0][r]);
        uint32_t p1 = pack_split(sm[q * 4 + 1][r]);
        uint32_t p2 = pack_split(sm[q * 4 + 2][r]);
        uint32_t p3 = pack_split(sm[q * 4 + 3][r]);
        size_t base = (size_t)(n0 + r) * DM + k0 + q * 4;
        *(uint2*)(oh + base) = make_uint2((p0 & 0xFFFFu) | ((p1 & 0xFFFFu) << 16),
                                          (p2 & 0xFFFFu) | ((p3 & 0xFFFFu) << 16));
        *(uint2*)(ol + base) = make_uint2((p0 >> 16) | (p1 & 0xFFFF0000u),
                                          (p2 >> 16) | (p3 & 0xFFFF0000u));
    }
}

// ===========================================================================
// QKV projection: 128x128 CTA, 8 warps (2m x 4n, warp 64x32), KC=64,
// 16 chunks, cp.async double-buffered.
// ===========================================================================
__global__ __launch_bounds__(256)
void proj_mma(const u16* __restrict__ inH, const u16* __restrict__ inL,
              const u16* __restrict__ wH, const u16* __restrict__ wL,
              const float* __restrict__ bq, const float* __restrict__ bk,
              const float* __restrict__ bv,
              u16* __restrict__ qH, u16* __restrict__ qL,
              u16* __restrict__ kH, u16* __restrict__ kL,
              u16* __restrict__ vH, u16* __restrict__ vL)
{
    constexpr int KC = 64, KSTR = KC / 2 + 4;  // 36 u32
    constexpr int PL = 128 * KSTR;             // plane u32 count (18432B)
    constexpr int BUF = 4 * PL;                // u32 per buffer set
    extern __shared__ uint32_t sm[];
    uint32_t sa = smem_u32(sm);

    const int z = blockIdx.z;
    const u16* A_H = inH + (size_t)z * (M_ROWS * DM);
    const u16* A_L = inL + (size_t)z * (M_ROWS * DM);
    const u16* W_H = wH + (size_t)z * (DM * DM);
    const u16* W_L = wL + (size_t)z * (DM * DM);
    const float* bias = (z == 0) ? bq : (z == 1) ? bk : bv;

    const int tid = threadIdx.x;
    const int wid = tid >> 5, lane = tid & 31;
    const int bm = blockIdx.x * 128;
    const int bn = blockIdx.y * 128;
    const int warp_m = (wid >> 2) * 64;
    const int warp_n = (wid & 3) * 32;

    float acc[4][4][4] = {};

    // prologue: fill chunk 0 into buffer 0
    fill_async<128, KC>(sa, sa + PL * 4, A_H + (size_t)bm * DM, A_L + (size_t)bm * DM, DM, tid);
    fill_async<128, KC>(sa + 2 * PL * 4, sa + 3 * PL * 4, W_H + (size_t)bn * DM, W_L + (size_t)bn * DM, DM, tid);
    CPC();

    #pragma unroll 1
    for (int c = 0; c < DM / KC; c++) {
        if (c + 1 < DM / KC) {
            uint32_t b = sa + ((c + 1) & 1) * BUF * 4;
            fill_async<128, KC>(b, b + PL * 4,
                                A_H + (size_t)bm * DM + (c + 1) * KC,
                                A_L + (size_t)bm * DM + (c + 1) * KC, DM, tid);
            fill_async<128, KC>(b + 2 * PL * 4, b + 3 * PL * 4,
                                W_H + (size_t)bn * DM + (c + 1) * KC,
                                W_L + (size_t)bn * DM + (c + 1) * KC, DM, tid);
            CPC();
            CPW(1);
        } else {
            CPW(0);
        }
        __syncthreads();
        uint32_t* buf = sm + (c & 1) * BUF;
        mma_chunk<4, 4, KC>(acc, buf, buf + PL, buf + 2 * PL, buf + 3 * PL,
                            warp_m, warp_n, lane);
        __syncthreads();
    }

    const int lr = lane >> 2, lc = (lane & 3) * 2;
    #pragma unroll
    for (int mt = 0; mt < 4; mt++) {
        #pragma unroll
        for (int nt = 0; nt < 4; nt++) {
            int col = bn + warp_n + nt * 8 + lc;
            float b0 = bias[col], b1 = bias[col + 1];
            int h = col >> 6, dh = col & 63;
            #pragma unroll
            for (int half = 0; half < 2; half++) {
                int r = bm + warp_m + mt * 16 + lr + half * 8;
                float v0 = acc[mt][nt][half * 2 + 0] + b0;
                float v1 = acc[mt][nt][half * 2 + 1] + b1;
                int b = r >> 11, s = r & (S_LEN - 1);
                int bh = b * NH + h;
                uint32_t p0 = pack_split(v0), p1 = pack_split(v1);
                if (z == 2) {
                    size_t t0 = ((size_t)bh * DH + dh) * S_LEN + s;
                    size_t t1 = ((size_t)bh * DH + dh + 1) * S_LEN + s;
                    vH[t0] = (u16)p0; vL[t0] = (u16)(p0 >> 16);
                    vH[t1] = (u16)p1; vL[t1] = (u16)(p1 >> 16);
                } else {
                    u16* dH = (z == 0) ? qH : kH;
                    u16* dL = (z == 0) ? qL : kL;
                    size_t base = ((size_t)bh * S_LEN + s) * DH + dh;
                    *(uint32_t*)(dH + base) = (p0 & 0xFFFFu) | ((p1 & 0xFFFFu) << 16);
                    *(uint32_t*)(dL + base) = (p0 >> 16) | (p1 & 0xFFFF0000u);
                }
            }
        }
    }
}

// ===========================================================================
// Scores: 128m x 64n CTA, 8 warps (4m x 2n, warp 32x32), K=64 single chunk.
// Fused partial-softmax stats: per-row (max, sumexp) over this 64-col tile.
// ===========================================================================
__global__ __launch_bounds__(256, 2)
void scores_mma(const u16* __restrict__ qH, const u16* __restrict__ qL,
                const u16* __restrict__ kH, const u16* __restrict__ kL,
                float* __restrict__ attn, float2* __restrict__ stats,
                float scale)
{
    constexpr int KC = 64, KSTR = KC / 2 + 4;
    constexpr int APL = 128 * KSTR;            // A plane u32
    constexpr int BPL = 64 * KSTR;             // B plane u32
    extern __shared__ uint32_t sm[];
    uint32_t sa = smem_u32(sm);
    uint32_t* Ah = sm;
    uint32_t* Al = Ah + APL;
    uint32_t* Bh = Al + APL;
    uint32_t* Bl = Bh + BPL;
    float2* sstat = (float2*)(Bl + BPL);       // [128][2]

    const int bh = blockIdx.z;
    const int tid = threadIdx.x;
    const int wid = tid >> 5, lane = tid & 31;
    const int bm = blockIdx.y * 128;
    const int bn = blockIdx.x * 64;
    const int warp_m = (wid >> 1) * 32;
    const int warp_n = (wid & 1) * 32;
    const size_t qoff = ((size_t)bh * S_LEN + bm) * DH;
    const size_t koff = ((size_t)bh * S_LEN + bn) * DH;
    float* ab = attn + (size_t)bh * S_LEN * S_LEN;

    fill_async<128, KC>(sa, sa + APL * 4, qH + qoff, qL + qoff, DH, tid);
    fill_async<64, KC>(sa + 2 * APL * 4, sa + (2 * APL + BPL) * 4, kH + koff, kL + koff, DH, tid);
    CPC();
    CPW(0);
    __syncthreads();

    float acc[2][4][4] = {};
    mma_chunk<2, 4, KC>(acc, Ah, Al, Bh, Bl, warp_m, warp_n, lane);

    const int lr = lane >> 2, lc = (lane & 3) * 2;
    // scale + store + per-row stats
    #pragma unroll
    for (int mt = 0; mt < 2; mt++) {
        #pragma unroll
        for (int half = 0; half < 2; half++) {
            int rl = warp_m + mt * 16 + lr + half * 8;   // row in CTA (0..127)
            int r = bm + rl;
            float v[8];
            #pragma unroll
            for (int nt = 0; nt < 4; nt++) {
                v[nt * 2 + 0] = acc[mt][nt][half * 2 + 0] * scale;
                v[nt * 2 + 1] = acc[mt][nt][half * 2 + 1] * scale;
                *(float2*)(ab + (size_t)r * S_LEN + bn + warp_n + nt * 8 + lc) =
                    make_float2(v[nt * 2], v[nt * 2 + 1]);
            }
            float m = v[0];
            #pragma unroll
            for (int j = 1; j < 8; j++) m = fmaxf(m, v[j]);
            m = fmaxf(m, __shfl_xor_sync(0xffffffffu, m, 1));
            m = fmaxf(m, __shfl_xor_sync(0xffffffffu, m, 2));
            float s = 0.f;
            #pragma unroll
            for (int j = 0; j < 8; j++) s += __expf(v[j] - m);
            s += __shfl_xor_sync(0xffffffffu, s, 1);
            s += __shfl_xor_sync(0xffffffffu, s, 2);
            if ((lane & 3) == 0) sstat[rl * 2 + (wid & 1)] = make_float2(m, s);
        }
    }
    __syncthreads();
    if (tid < 128) {
        float2 a = sstat[tid * 2 + 0], b = sstat[tid * 2 + 1];
        float M = fmaxf(a.x, b.x);
        float S = a.y * __expf(a.x - M) + b.y * __expf(b.x - M);
        stats[((size_t)bh * S_LEN + bm + tid) * 32 + blockIdx.x] = make_float2(M, S);
    }
}

// ===========================================================================
// Stats reduce: 32 tiles -> (M, 1/S) per row
// ===========================================================================
__global__ __launch_bounds__(256)
void reduce_stats(const float2* __restrict__ stats, float2* __restrict__ rowst)
{
    int row = blockIdx.x * 256 + threadIdx.x;   // 0..65535
    const float2* p = stats + (size_t)row * 32;
    float M = -1e30f;
    #pragma unroll
    for (int t = 0; t < 32; t++) M = fmaxf(M, p[t].x);
    float S = 0.f;
    #pragma unroll
    for (int t = 0; t < 32; t++) S += p[t].y * __expf(p[t].x - M);
    rowst[row] = make_float2(M, 1.0f / S);
}

// ===========================================================================
// AV: softmax-apply fused. 128m x 64n CTA, 8 warps (4m x 2n, warp 32x32),
// KC=128, 16 chunks. Writes normalized attn + packed o.
// ===========================================================================
__global__ __launch_bounds__(256, 2)
void av_mma(float* __restrict__ attn, const u16* __restrict__ vH,
            const u16* __restrict__ vL, const float2* __restrict__ rowst,
            u16* __restrict__ oH, u16* __restrict__ oL)
{
    constexpr int KC = 128, KSTR = KC / 2 + 4;  // 68
    constexpr int APL = 128 * KSTR;
    constexpr int BPL = 64 * KSTR;
    extern __shared__ uint32_t sm[];
    uint32_t* Ah = sm;
    uint32_t* Al = Ah + APL;
    uint32_t* Bh = Al + APL;
    uint32_t* Bl = Bh + BPL;

    const int bh = blockIdx.z;
    const int bb = bh >> 4, h = bh & 15;
    const int tid = threadIdx.x;
    const int wid = tid >> 5, lane = tid & 31;
    const int bm = blockIdx.x * 128;
    const int warp_m = (wid >> 1) * 32;
    const int warp_n = (wid & 1) * 32;
    float* ab = attn + ((size_t)bh * S_LEN + bm) * S_LEN;
    const u16* vbH = vH + (size_t)bh * DH * S_LEN;
    const u16* vbL = vL + (size_t)bh * DH * S_LEN;
    const float2* rs = rowst + (size_t)bh * S_LEN + bm;

    float acc[2][4][4] = {};

    #pragma unroll 1
    for (int c = 0; c < S_LEN / KC; c++) {
        fill_softmax<128, KC>(Ah, Al, ab + c * KC, S_LEN, rs, tid);
        fill_u16<64, KC>(Bh, Bl, vbH + c * KC, vbL + c * KC, S_LEN, tid);
        __syncthreads();
        mma_chunk<2, 4, KC>(acc, Ah, Al, Bh, Bl, warp_m, warp_n, lane);
        __syncthreads();
    }

    const int lr = lane >> 2, lc = (lane & 3) * 2;
    #pragma unroll
    for (int mt = 0; mt < 2; mt++) {
        #pragma unroll
        for (int nt = 0; nt < 4; nt++) {
            int col = warp_n + nt * 8 + lc;     // dh
            #pragma unroll
            for (int half = 0; half < 2; half++) {
                int s = bm + warp_m + mt * 16 + lr + half * 8;
                uint32_t p0 = pack_split(acc[mt][nt][half * 2 + 0]);
                uint32_t p1 = pack_split(acc[mt][nt][half * 2 + 1]);
                size_t base = ((size_t)bb * S_LEN + s) * DM + h * DH + col;
                *(uint32_t*)(oH + base) = (p0 & 0xFFFFu) | ((p1 & 0xFFFFu) << 16);
                *(uint32_t*)(oL + base) = (p0 >> 16) | (p1 & 0xFFFF0000u);
            }
        }
    }
}

// ===========================================================================
// Output projection: cp.async double-buffered, fp32 out.
// ===========================================================================
__global__ __launch_bounds__(256)
void out_mma(const u16* __restrict__ aH, const u16* __restrict__ aL,
             const u16* __restrict__ wH, const u16* __restrict__ wL,
             const float* __restrict__ bo, float* __restrict__ out)
{
    constexpr int KC = 64, KSTR = KC / 2 + 4;
    constexpr int PL = 128 * KSTR;
    constexpr int BUF = 4 * PL;
    extern __shared__ uint32_t sm[];
    uint32_t sa = smem_u32(sm);

    const int tid = threadIdx.x;
    const int wid = tid >> 5, lane = tid & 31;
    const int bm = blockIdx.x * 128;
    const int bn = blockIdx.y * 128;
    const int warp_m = (wid >> 2) * 64;
    const int warp_n = (wid & 3) * 32;

    float acc[4][4][4] = {};

    fill_async<128, KC>(sa, sa + PL * 4, aH + (size_t)bm * DM, aL + (size_t)bm * DM, DM, tid);
    fill_async<128, KC>(sa + 2 * PL * 4, sa + 3 * PL * 4, wH + (size_t)bn * DM, wL + (size_t)bn * DM, DM, tid);
    CPC();

    #pragma unroll 1
    for (int c = 0; c < DM / KC; c++) {
        if (c + 1 < DM / KC) {
            uint32_t b = sa + ((c + 1) & 1) * BUF * 4;
            fill_async<128, KC>(b, b + PL * 4,
                                aH + (size_t)bm * DM + (c + 1) * KC,
                                aL + (size_t)bm * DM + (c + 1) * KC, DM, tid);
            fill_async<128, KC>(b + 2 * PL * 4, b + 3 * PL * 4,
                                wH + (size_t)bn * DM + (c + 1) * KC,
                                wL + (size_t)bn * DM + (c + 1) * KC, DM, tid);
            CPC();
            CPW(1);
        } else {
            CPW(0);
        }
        __syncthreads();
        uint32_t* buf = sm + (c & 1) * BUF;
        mma_chunk<4, 4, KC>(acc, buf, buf + PL, buf + 2 * PL, buf + 3 * PL,
                            warp_m, warp_n, lane);
        __syncthreads();
    }

    const int lr = lane >> 2, lc = (lane & 3) * 2;
    #pragma unroll
    for (int mt = 0; mt < 4; mt++) {
        #pragma unroll
        for (int nt = 0; nt < 4; nt++) {
            int col = bn + warp_n + nt * 8 + lc;
            float b0 = bo[col], b1 = bo[col + 1];
            #pragma unroll
            for (int half = 0; half < 2; half++) {
                int r = bm + warp_m + mt * 16 + lr + half * 8;
                *(float2*)(out + (size_t)r * DM + col) =
                    make_float2(acc[mt][nt][half * 2 + 0] + b0,
                                acc[mt][nt][half * 2 + 1] + b1);
            }
        }
    }
}

// ===========================================================================
// Launch
// ===========================================================================
extern "C" void kernel_launch(void* const* d_in, const int* in_sizes, int n_in,
                              void* d_out, int out_size)
{
    const float* Q  = (const float*)d_in[0];
    const float* K  = (const float*)d_in[1];
    const float* V  = (const float*)d_in[2];
    const float* Wq = (const float*)d_in[3];
    const float* bq = (const float*)d_in[4];
    const float* Wk = (const float*)d_in[5];
    const float* bk = (const float*)d_in[6];
    const float* Wv = (const float*)d_in[7];
    const float* bv = (const float*)d_in[8];
    const float* Wo = (const float*)d_in[9];
    const float* bo = (const float*)d_in[10];

    float* out  = (float*)d_out;
    float* attn = out + OUT_ELEMS;

    u16 *inH, *inL, *wH, *wL, *qH, *qL, *kH, *kL, *vH, *vL, *oH, *oL;
    float2 *stats, *rowst;
    cudaGetSymbolAddress((void**)&inH, g_inH);
    cudaGetSymbolAddress((void**)&inL, g_inL);
    cudaGetSymbolAddress((void**)&wH, g_wH);
    cudaGetSymbolAddress((void**)&wL, g_wL);
    cudaGetSymbolAddress((void**)&qH, g_qH);
    cudaGetSymbolAddress((void**)&qL, g_qL);
    cudaGetSymbolAddress((void**)&kH, g_kH);
    cudaGetSymbolAddress((void**)&kL, g_kL);
    cudaGetSymbolAddress((void**)&vH, g_vH);
    cudaGetSymbolAddress((void**)&vL, g_vL);
    cudaGetSymbolAddress((void**)&oH, g_oH);
    cudaGetSymbolAddress((void**)&oL, g_oL);
    cudaGetSymbolAddress((void**)&stats, g_stats);
    cudaGetSymbolAddress((void**)&rowst, g_row);

    const int KSTR64 = 64 / 2 + 4, KSTR128 = 128 / 2 + 4;
    const int SM_PROJ = 2 * 4 * 128 * KSTR64 * 4;                    // 147456
    const int SM_SC   = (2 * 128 + 2 * 64) * KSTR64 * 4 + 128 * 16;  // 57344
    const int SM_AV   = (2 * 128 + 2 * 64) * KSTR128 * 4;            // 104448
    cudaFuncSetAttribute(proj_mma, cudaFuncAttributeMaxDynamicSharedMemorySize, SM_PROJ);
    cudaFuncSetAttribute(out_mma, cudaFuncAttributeMaxDynamicSharedMemorySize, SM_PROJ);
    cudaFuncSetAttribute(scores_mma, cudaFuncAttributeMaxDynamicSharedMemorySize, SM_SC);
    cudaFuncSetAttribute(av_mma, cudaFuncAttributeMaxDynamicSharedMemorySize, SM_AV);

    convert_in<<<dim3(M_ROWS * DM / 8 / 256, 3), 256>>>(Q, K, V, inH, inL);
    convert_w<<<dim3(DM / 64, DM / 64, 4), 256>>>(Wq, Wk, Wv, Wo, wH, wL);

    proj_mma<<<dim3(M_ROWS / 128, DM / 128, 3), 256, SM_PROJ>>>(
        inH, inL, wH, wL, bq, bk, bv, qH, qL, kH, kL, vH, vL);

    scores_mma<<<dim3(S_LEN / 64, S_LEN / 128, BH), 256, SM_SC>>>(
        qH, qL, kH, kL, attn, stats, 0.125f);

    reduce_stats<<<BH * S_LEN / 256, 256>>>(stats, rowst);

    av_mma<<<dim3(S_LEN / 128, 1, BH), 256, SM_AV>>>(
        attn, vH, vL, rowst, oH, oL);

    out_mma<<<dim3(M_ROWS / 128, DM / 128), 256, SM_PROJ>>>(
        oH, oL, wH + 3 * (size_t)(DM * DM), wL + 3 * (size_t)(DM * DM), bo, out);
}